// round 8
// baseline (speedup 1.0000x reference)
#include <cuda_runtime.h>
#include <cuda_fp16.h>
#include <cstdint>

// ---------------------------------------------------------------------------
// Problem constants
// ---------------------------------------------------------------------------
#define CIN     512
#define COUT    512
#define LIN     4096
#define KT      7
#define OUTL    4090
#define BATCH   4

// Tiling: CTA = 128 (d) x 128 (o), K-chunk 32 c per step, 112 steps total.
// 256 threads, 8 warps (4 m x 2 n), warp tile 32x64. 2 CTAs/SM.
#define BM      128
#define BN      128
#define BK      32
#define NSTEPS  (CIN / BK * KT)   // 112
#define THREADS 256

// SMEM layout (bytes). A: 3 stages x 128 rows x 80B. B: 2 stages x 128 x 80B.
// xs: 2 stages x 32 rows x 136 floats (544B rows, 16B-aligned).
// Row stride 80B => (5*r mod 8) 16B-bank map, conflict-free ldmatrix.
#define AROW    80
#define ASTG    (BM * AROW)        // 10240
#define BSTG    (BN * AROW)        // 10240
#define XROWF   136                // floats per xs row (544B)
#define XROWB   544
#define XSTG    (BK * XROWB)       // 17408

#define A_OFF   0                  // 3 * ASTG = 30720
#define B_OFF   30720              // 2 * BSTG = 20480
#define XS_OFF  51200              // 2 * XSTG = 34816
#define G01_OFF 86016              // 7*128*8 = 7168
#define JSM_OFF 93184              // 7*128*4 = 3584
#define SMEM_TOTAL 96768

// ---------------------------------------------------------------------------
// Scratch (no allocations allowed -> __device__ globals)
// ---------------------------------------------------------------------------
__device__ __half g_wh[(size_t)KT * COUT * CIN];   // [k][d][c] fp16
__device__ float  g_g0[(size_t)BATCH * 4096 * KT];
__device__ float  g_g1[(size_t)BATCH * 4096 * KT];
__device__ int    g_j0[(size_t)BATCH * 4096 * KT];

// ---------------------------------------------------------------------------
// Helpers
// ---------------------------------------------------------------------------
__device__ __forceinline__ uint32_t smem_u32(const void* p) {
    uint32_t a;
    asm("{ .reg .u64 t; cvta.to.shared.u64 t, %1; cvt.u32.u64 %0, t; }" : "=r"(a) : "l"(p));
    return a;
}
__device__ __forceinline__ void cp16(uint32_t dst, const void* src) {
    asm volatile("cp.async.cg.shared.global [%0], [%1], 16;" :: "r"(dst), "l"(src));
}
__device__ __forceinline__ void cp16z(uint32_t dst, const void* src, int nbytes) {
    asm volatile("cp.async.cg.shared.global [%0], [%1], 16, %2;"
                 :: "r"(dst), "l"(src), "r"(nbytes));
}
#define CP_COMMIT() asm volatile("cp.async.commit_group;" ::: "memory")
#define CP_WAIT(N)  asm volatile("cp.async.wait_group %0;" :: "n"(N) : "memory")

__device__ __forceinline__ void ldsm4(uint32_t& r0, uint32_t& r1, uint32_t& r2,
                                      uint32_t& r3, uint32_t addr) {
    asm volatile("ldmatrix.sync.aligned.m8n8.x4.shared.b16 {%0,%1,%2,%3}, [%4];"
                 : "=r"(r0), "=r"(r1), "=r"(r2), "=r"(r3) : "r"(addr));
}
__device__ __forceinline__ void mma_f16(float c[4], const uint32_t a[4],
                                        uint32_t b0, uint32_t b1) {
    asm volatile(
        "mma.sync.aligned.m16n8k16.row.col.f32.f16.f16.f32 "
        "{%0,%1,%2,%3}, {%4,%5,%6,%7}, {%8,%9}, {%0,%1,%2,%3};\n"
        : "+f"(c[0]), "+f"(c[1]), "+f"(c[2]), "+f"(c[3])
        : "r"(a[0]), "r"(a[1]), "r"(a[2]), "r"(a[3]), "r"(b0), "r"(b1));
}

// ---------------------------------------------------------------------------
// Prep 1: weight transpose w[d][c][k] -> g_wh[k][d][c] fp16
// ---------------------------------------------------------------------------
__global__ void prep_weight(const float* __restrict__ w) {
    int i = blockIdx.x * blockDim.x + threadIdx.x;
    const int total = KT * COUT * CIN;
    if (i >= total) return;
    int c = i & (CIN - 1);
    int d = (i >> 9) & (COUT - 1);
    int k = i / (COUT * CIN);
    g_wh[i] = __float2half(w[((size_t)d * CIN + c) * KT + k]);
}

// ---------------------------------------------------------------------------
// Prep 2: gather params per (b, o, k). Padded o in [OUTL,4096) -> zeros.
// ---------------------------------------------------------------------------
__global__ void prep_gather(const float* __restrict__ off) {
    int i = blockIdx.x * blockDim.x + threadIdx.x;
    const int total = BATCH * 4096 * KT;
    if (i >= total) return;
    int k = i % KT;
    int o = (i / KT) & 4095;
    int b = i / (KT * 4096);
    float gg0 = 0.f, gg1 = 0.f;
    int j0 = 0;
    if (o < OUTL) {
        float T = (float)(o + k) + off[((size_t)b * OUTL + o) * KT + k];
        T = fmaxf(T, (float)o);
        T = fminf(T, (float)(o + (KT - 1)));
        int U0 = (int)floorf(T);
        if (U0 < 0) U0 = 0;
        if (U0 > LIN - 2) U0 = LIN - 2;
        gg0 = fmaxf(0.f, 1.f - fabsf((float)U0 - T));
        gg1 = fmaxf(0.f, 1.f - fabsf((float)(U0 + 1) - T));
        j0 = U0 - o;
    }
    g_j0[i] = j0;
    g_g0[i] = gg0;
    g_g1[i] = gg1;
}

// ---------------------------------------------------------------------------
// Main: fp16 mma.sync m16n8k16 fused gather-GEMM, 2 CTAs/SM.
// 8 warps: wm = wid&3 (m 32 each), wn = wid>>2 (n 64 each).
// Pipeline: A triple-buffered cp.async (dist 2); xs double-buffered cp.async
// (issued at k==4, consumed 2 steps later); B (samp) double-buffered, built in
// SMEM by all threads each step for step s+1.
// ---------------------------------------------------------------------------
__global__ __launch_bounds__(THREADS, 2)
void deform_mma(const float* __restrict__ x, const float* __restrict__ bias,
                float* __restrict__ out) {
    extern __shared__ char smem[];
    const uint32_t sbase = smem_u32(smem);
    float2* g01 = (float2*)(smem + G01_OFF);
    int*    jsm = (int*)(smem + JSM_OFF);

    const int tid  = threadIdx.x;
    const int lane = tid & 31;
    const int wid  = tid >> 5;
    const int o0 = blockIdx.x * BN;
    const int d0 = blockIdx.y * BM;
    const int b  = blockIdx.z;

    const int m_base = (wid & 3) * 32;
    const int n_base = (wid >> 2) * 64;

    // ---- stage gather params for this o-tile ----
    for (int i = tid; i < KT * BN; i += THREADS) {
        int k = i >> 7, o = i & 127;
        int gi = ((b * 4096) + o0 + o) * KT + k;
        jsm[i] = g_j0[gi];
        g01[i] = make_float2(g_g0[gi], g_g1[gi]);
    }

    // ---- prologue: A[0]->buf0, A[1]->buf1, xs chunk0 ----
    {
#pragma unroll
        for (int st = 0; st < 2; ++st) {
            const __half* wsrc = g_wh + ((size_t)st * COUT + d0) * CIN;  // k=st, c0=0
            uint32_t dbase = sbase + A_OFF + st * ASTG;
#pragma unroll
            for (int it = 0; it < 2; ++it) {
                int i = tid + it * THREADS;
                int r = i >> 2, ch = i & 3;
                cp16(dbase + r * AROW + ch * 16, wsrc + (size_t)r * CIN + ch * 8);
            }
        }
        uint32_t dxb = sbase + XS_OFF;     // chunk 0 -> xs buf 0
        for (int i = tid; i < 1088; i += THREADS) {
            int r = i / 34, q = i - r * 34;
            int gt0 = o0 + q * 4;
            const float* src = x + ((size_t)(b * CIN + r)) * LIN + gt0;
            int rem = LIN - gt0;
            int nv = rem >= 4 ? 16 : (rem > 0 ? rem * 4 : 0);
            if (nv == 0) src = x;
            cp16z(dxb + r * XROWB + q * 16, src, nv);
        }
        CP_COMMIT();
        CP_WAIT(0);
        __syncthreads();
        // build B[0] (k=0, chunk 0) into B buf 0
        const float* xsf = (const float*)(smem + XS_OFF);
#pragma unroll
        for (int it = 0; it < 2; ++it) {
            int i = tid + it * THREADS;
            int o = i & 127, cb = i >> 7;
            int j = jsm[o];
            float2 g = g01[o];
            int base = cb * 8 * XROWF + o + j;
            __half2 h[4];
#pragma unroll
            for (int i2 = 0; i2 < 4; ++i2) {
                float v0 = g.x * xsf[base + (2 * i2) * XROWF]     + g.y * xsf[base + (2 * i2) * XROWF + 1];
                float v1 = g.x * xsf[base + (2 * i2 + 1) * XROWF] + g.y * xsf[base + (2 * i2 + 1) * XROWF + 1];
                h[i2] = __floats2half2_rn(v0, v1);
            }
            *reinterpret_cast<uint4*>(smem + B_OFF + o * AROW + cb * 16)
                = *reinterpret_cast<uint4*>(h);
        }
        __syncthreads();
    }

    float acc[2][8][4];
#pragma unroll
    for (int mi = 0; mi < 2; ++mi)
#pragma unroll
        for (int ni = 0; ni < 8; ++ni)
#pragma unroll
            for (int q = 0; q < 4; ++q) acc[mi][ni][q] = 0.f;

    // ---- mainloop ----
    for (int cc = 0; cc < 16; ++cc) {
#pragma unroll
        for (int k = 0; k < KT; ++k) {
            const int s = cc * KT + k;
            // issue A for step s+2 (wraps harmlessly at the tail)
            {
                int k2 = k + 2, cc2 = cc;
                if (k2 >= KT) { k2 -= KT; cc2 += 1; }
                if (cc2 >= 16) { cc2 = 0; k2 = 0; }
                const int buf = (s + 2) % 3;
                const __half* wsrc = g_wh + ((size_t)k2 * COUT + d0) * CIN + cc2 * BK;
                uint32_t dbase = sbase + A_OFF + buf * ASTG;
#pragma unroll
                for (int it = 0; it < 2; ++it) {
                    int i = tid + it * THREADS;
                    int r = i >> 2, ch = i & 3;
                    cp16(dbase + r * AROW + ch * 16, wsrc + (size_t)r * CIN + ch * 8);
                }
            }
            // issue xs for chunk cc+1 two steps before it is consumed
            if (k == 4 && cc + 1 < 16) {
                const int cn = cc + 1;
                uint32_t dxb = sbase + XS_OFF + (cn & 1) * XSTG;
                for (int i = tid; i < 1088; i += THREADS) {
                    int r = i / 34, q = i - r * 34;
                    int gt0 = o0 + q * 4;
                    const float* src = x + ((size_t)(b * CIN + cn * BK + r)) * LIN + gt0;
                    int rem = LIN - gt0;
                    int nv = rem >= 4 ? 16 : (rem > 0 ? rem * 4 : 0);
                    if (nv == 0) src = x;
                    cp16z(dxb + r * XROWB + q * 16, src, nv);
                }
            }
            CP_COMMIT();
            CP_WAIT(2);        // 3 groups pending after commit -> forces A[s] (+xs)
            __syncthreads();

            // ---- mma for step s ----
            {
                uint32_t abase = sbase + A_OFF + (s % 3) * ASTG;
                uint32_t bbase = sbase + B_OFF + (s & 1) * BSTG;
#pragma unroll
                for (int kk = 0; kk < 2; ++kk) {
                    uint32_t afr[2][4];
#pragma unroll
                    for (int mi = 0; mi < 2; ++mi) {
                        uint32_t addr = abase
                            + (uint32_t)(m_base + mi * 16 + (lane & 15)) * AROW
                            + kk * 32 + (lane & 16);
                        ldsm4(afr[mi][0], afr[mi][1], afr[mi][2], afr[mi][3], addr);
                    }
                    uint32_t bfr[8][2];
#pragma unroll
                    for (int nb = 0; nb < 4; ++nb) {
                        uint32_t addr = bbase
                            + (uint32_t)(n_base + nb * 16 + (lane & 7) + ((lane & 16) >> 1)) * AROW
                            + kk * 32 + ((lane & 8) << 1);
                        ldsm4(bfr[2 * nb][0], bfr[2 * nb][1],
                              bfr[2 * nb + 1][0], bfr[2 * nb + 1][1], addr);
                    }
#pragma unroll
                    for (int ni = 0; ni < 8; ++ni) {
                        mma_f16(acc[0][ni], afr[0], bfr[ni][0], bfr[ni][1]);
                        mma_f16(acc[1][ni], afr[1], bfr[ni][0], bfr[ni][1]);
                    }
                }
            }

            // ---- build B[s+1] into the other B buffer ----
            if (s + 1 < NSTEPS) {
                const int kn = (k + 1 < KT) ? k + 1 : 0;
                const int cn = (k + 1 < KT) ? cc : cc + 1;
                const float* xsf = (const float*)(smem + XS_OFF + (cn & 1) * XSTG);
#pragma unroll
                for (int it = 0; it < 2; ++it) {
                    int i = tid + it * THREADS;
                    int o = i & 127, cb = i >> 7;
                    int j = jsm[kn * BN + o];
                    float2 g = g01[kn * BN + o];
                    int base = cb * 8 * XROWF + o + j;
                    __half2 h[4];
#pragma unroll
                    for (int i2 = 0; i2 < 4; ++i2) {
                        float v0 = g.x * xsf[base + (2 * i2) * XROWF]
                                 + g.y * xsf[base + (2 * i2) * XROWF + 1];
                        float v1 = g.x * xsf[base + (2 * i2 + 1) * XROWF]
                                 + g.y * xsf[base + (2 * i2 + 1) * XROWF + 1];
                        h[i2] = __floats2half2_rn(v0, v1);
                    }
                    *reinterpret_cast<uint4*>(smem + B_OFF + ((s + 1) & 1) * BSTG
                                              + o * AROW + cb * 16)
                        = *reinterpret_cast<uint4*>(h);
                }
            }
            __syncthreads();
        }
    }

    // ---- epilogue: bias add + store ----
    const int qg = lane >> 2, tq = lane & 3;
#pragma unroll
    for (int mi = 0; mi < 2; ++mi) {
        int d = d0 + m_base + mi * 16 + qg;
        float bz0 = bias[d];
        float bz1 = bias[d + 8];
        size_t row0 = ((size_t)b * COUT + d) * OUTL;
        size_t row1 = row0 + (size_t)8 * OUTL;
#pragma unroll
        for (int ni = 0; ni < 8; ++ni) {
            int col = o0 + n_base + ni * 8 + 2 * tq;
            if (col < OUTL) {   // col even, OUTL even => col+1 < OUTL too
                float2 v0 = make_float2(acc[mi][ni][0] + bz0, acc[mi][ni][1] + bz0);
                float2 v1 = make_float2(acc[mi][ni][2] + bz1, acc[mi][ni][3] + bz1);
                *reinterpret_cast<float2*>(out + row0 + col) = v0;
                *reinterpret_cast<float2*>(out + row1 + col) = v1;
            }
        }
    }
}

// ---------------------------------------------------------------------------
extern "C" void kernel_launch(void* const* d_in, const int* in_sizes, int n_in,
                              void* d_out, int out_size) {
    const float* x    = (const float*)d_in[0];
    const float* off  = (const float*)d_in[1];
    const float* w    = (const float*)d_in[2];
    const float* bias = (const float*)d_in[3];
    float* out = (float*)d_out;

    {
        int total = KT * COUT * CIN;
        prep_weight<<<(total + 255) / 256, 256>>>(w);
    }
    {
        int total = BATCH * 4096 * KT;
        prep_gather<<<(total + 255) / 256, 256>>>(off);
    }

    cudaFuncSetAttribute(deform_mma, cudaFuncAttributeMaxDynamicSharedMemorySize,
                         SMEM_TOTAL);
    dim3 grid(4096 / BN, COUT / BM, BATCH);   // 32 x 4 x 4 = 512 CTAs
    deform_mma<<<grid, THREADS, SMEM_TOTAL>>>(x, bias, out);
}

// round 10
// speedup vs baseline: 1.1169x; 1.1169x over previous
#include <cuda_runtime.h>
#include <cuda_fp16.h>
#include <cstdint>

// ---------------------------------------------------------------------------
// Problem constants
// ---------------------------------------------------------------------------
#define CIN     512
#define COUT    512
#define LIN     4096
#define KT      7
#define OUTL    4090
#define BATCH   4

// Tiling: CTA = 256 (d) x 128 (o). K-step = 64 (32 c x 2 taps), 4 steps per
// c-chunk (last is K=32), 64 steps total. 512 threads, 16 warps (8m x 2n).
#define BM      256
#define BN      128
#define BK      32
#define THREADS 512

// SMEM layout (bytes). Row stride 144B = 9 x 16B -> bank(r) = r mod 8,
// conflict-free ldmatrix. A: 3 stages x 256 x 144. B: 2 stages x 128 x 144.
// xs: 2 stages x 32 rows x 136 floats.
#define AROW    144
#define ASTG    (BM * AROW)        // 36864
#define BSTG    (BN * AROW)        // 18432
#define XROWF   136
#define XROWB   544
#define XSTG    (BK * XROWB)       // 17408

#define A_OFF   0                  // 3 * ASTG = 110592
#define B_OFF   110592             // 2 * BSTG = 36864
#define XS_OFF  147456             // 2 * XSTG = 34816
#define G01_OFF 182272             // 7*128*8 = 7168
#define JSM_OFF 189440             // 7*128*4 = 3584
#define SMEM_TOTAL 193024

// ---------------------------------------------------------------------------
// Scratch (no allocations allowed -> __device__ globals)
// ---------------------------------------------------------------------------
__device__ __half g_wh[(size_t)KT * COUT * CIN];   // [k][d][c] fp16
__device__ float  g_g0[(size_t)BATCH * 4096 * KT];
__device__ float  g_g1[(size_t)BATCH * 4096 * KT];
__device__ int    g_j0[(size_t)BATCH * 4096 * KT];

// ---------------------------------------------------------------------------
// Helpers
// ---------------------------------------------------------------------------
__device__ __forceinline__ uint32_t smem_u32(const void* p) {
    uint32_t a;
    asm("{ .reg .u64 t; cvta.to.shared.u64 t, %1; cvt.u32.u64 %0, t; }" : "=r"(a) : "l"(p));
    return a;
}
__device__ __forceinline__ void cp16(uint32_t dst, const void* src) {
    asm volatile("cp.async.cg.shared.global [%0], [%1], 16;" :: "r"(dst), "l"(src));
}
__device__ __forceinline__ void cp16z(uint32_t dst, const void* src, int nbytes) {
    asm volatile("cp.async.cg.shared.global [%0], [%1], 16, %2;"
                 :: "r"(dst), "l"(src), "r"(nbytes));
}
#define CP_COMMIT() asm volatile("cp.async.commit_group;" ::: "memory")
#define CP_WAIT(N)  asm volatile("cp.async.wait_group %0;" :: "n"(N) : "memory")

__device__ __forceinline__ void ldsm4(uint32_t& r0, uint32_t& r1, uint32_t& r2,
                                      uint32_t& r3, uint32_t addr) {
    asm volatile("ldmatrix.sync.aligned.m8n8.x4.shared.b16 {%0,%1,%2,%3}, [%4];"
                 : "=r"(r0), "=r"(r1), "=r"(r2), "=r"(r3) : "r"(addr));
}
__device__ __forceinline__ void mma_f16(float c[4], const uint32_t a[4],
                                        uint32_t b0, uint32_t b1) {
    asm volatile(
        "mma.sync.aligned.m16n8k16.row.col.f32.f16.f16.f32 "
        "{%0,%1,%2,%3}, {%4,%5,%6,%7}, {%8,%9}, {%0,%1,%2,%3};\n"
        : "+f"(c[0]), "+f"(c[1]), "+f"(c[2]), "+f"(c[3])
        : "r"(a[0]), "r"(a[1]), "r"(a[2]), "r"(a[3]), "r"(b0), "r"(b1));
}

// ---------------------------------------------------------------------------
// Fused prep: blocks [0,896) transpose weights (8 outputs/thread);
// blocks [896,1344) compute gather params.
// ---------------------------------------------------------------------------
__global__ void prep_all(const float* __restrict__ w, const float* __restrict__ off) {
    if (blockIdx.x < 896) {
        int i = blockIdx.x * 256 + threadIdx.x;       // 229376 threads x 8 outs
        int c0 = (i * 8) & 511;
        int d  = ((i * 8) >> 9) & 511;
        int k  = (i * 8) / (COUT * CIN);
        const float* src = w + ((size_t)d * CIN + c0) * KT + k;
        __half h[8];
#pragma unroll
        for (int q = 0; q < 8; ++q) h[q] = __float2half(src[q * KT]);
        *reinterpret_cast<uint4*>(g_wh + ((size_t)k * COUT + d) * CIN + c0)
            = *reinterpret_cast<const uint4*>(h);
    } else {
        int i = (blockIdx.x - 896) * 256 + threadIdx.x;   // 114688 total
        int k = i % KT;
        int o = (i / KT) & 4095;
        int b = i / (KT * 4096);
        float gg0 = 0.f, gg1 = 0.f;
        int j0 = 0;
        if (o < OUTL) {
            float T = (float)(o + k) + off[((size_t)b * OUTL + o) * KT + k];
            T = fmaxf(T, (float)o);
            T = fminf(T, (float)(o + (KT - 1)));
            int U0 = (int)floorf(T);
            if (U0 < 0) U0 = 0;
            if (U0 > LIN - 2) U0 = LIN - 2;
            gg0 = fmaxf(0.f, 1.f - fabsf((float)U0 - T));
            gg1 = fmaxf(0.f, 1.f - fabsf((float)(U0 + 1) - T));
            j0 = U0 - o;
        }
        g_j0[i] = j0;
        g_g0[i] = gg0;
        g_g1[i] = gg1;
    }
}

// ---------------------------------------------------------------------------
// A-tile loader: rows d0..d0+255, K cols = [tap kbase c0..c0+31 | tap kbase+1].
// ---------------------------------------------------------------------------
__device__ __forceinline__ void load_A(uint32_t dbase, int kbase, int kcount,
                                       int c0, int d0, int tid) {
    if (kcount == 2) {
#pragma unroll
        for (int it = 0; it < 4; ++it) {
            int i = tid + it * THREADS;
            int r = i >> 3, ch = i & 7;
            int tap = kbase + (ch >> 2);
            cp16(dbase + r * AROW + ch * 16,
                 g_wh + ((size_t)tap * COUT + d0 + r) * CIN + c0 + (ch & 3) * 8);
        }
    } else {
#pragma unroll
        for (int it = 0; it < 2; ++it) {
            int i = tid + it * THREADS;
            int r = i >> 2, ch = i & 3;
            cp16(dbase + r * AROW + ch * 16,
                 g_wh + ((size_t)kbase * COUT + d0 + r) * CIN + c0 + ch * 8);
        }
    }
}

// ---------------------------------------------------------------------------
// B-tile builder: B[o][kappa], kappa = (tap-kbase)*32 + c. 8 halves per write.
// ---------------------------------------------------------------------------
__device__ __forceinline__ void build_B(char* smem, int boff, const float* xsf,
                                        const float2* g01, const int* jsm,
                                        int kbase, int kcount, int tid) {
#pragma unroll
    for (int it = 0; it < 2; ++it) {
        if (it == 1 && kcount == 1) break;
        int i = tid + it * THREADS;
        int o = i & 127;
        int cb = i >> 7;                 // 0..7 (0..3 if kcount==1)
        int tap = kbase + (cb >> 2);
        int base = (cb & 3) * 8 * XROWF + o + jsm[tap * 128 + o];
        float2 g = g01[tap * 128 + o];
        __half2 h[4];
#pragma unroll
        for (int q = 0; q < 4; ++q) {
            float v0 = g.x * xsf[base + (2 * q) * XROWF]
                     + g.y * xsf[base + (2 * q) * XROWF + 1];
            float v1 = g.x * xsf[base + (2 * q + 1) * XROWF]
                     + g.y * xsf[base + (2 * q + 1) * XROWF + 1];
            h[q] = __floats2half2_rn(v0, v1);
        }
        *reinterpret_cast<uint4*>(smem + boff + o * AROW + cb * 16)
            = *reinterpret_cast<uint4*>(h);
    }
}

// ---------------------------------------------------------------------------
// xs loader (cp.async): 32 c-rows x 136-float window at o0.
// ---------------------------------------------------------------------------
__device__ __forceinline__ void load_xs(uint32_t dxb, const float* x, int b,
                                        int c0, int o0, int tid) {
    for (int i = tid; i < 1088; i += THREADS) {
        int r = i / 34, q = i - r * 34;
        int gt0 = o0 + q * 4;
        const float* src = x + ((size_t)(b * CIN + c0 + r)) * LIN + gt0;
        int rem = LIN - gt0;
        int nv = rem >= 4 ? 16 : (rem > 0 ? rem * 4 : 0);
        if (nv == 0) src = x;
        cp16z(dxb + r * XROWB + q * 16, src, nv);
    }
}

// ---------------------------------------------------------------------------
// Main: fp16 mma.sync m16n8k16 fused gather-GEMM, K=64 per step.
// ---------------------------------------------------------------------------
__global__ __launch_bounds__(THREADS, 1)
void deform_mma(const float* __restrict__ x, const float* __restrict__ bias,
                float* __restrict__ out) {
    extern __shared__ char smem[];
    const uint32_t sbase = smem_u32(smem);
    float2* g01 = (float2*)(smem + G01_OFF);
    int*    jsm = (int*)(smem + JSM_OFF);

    const int tid  = threadIdx.x;
    const int lane = tid & 31;
    const int wid  = tid >> 5;
    const int o0 = blockIdx.x * BN;
    const int d0 = blockIdx.y * BM;
    const int b  = blockIdx.z;

    const int m_base = (wid & 7) * 32;
    const int n_base = (wid >> 3) * 64;

    // ---- stage gather params ----
    for (int i = tid; i < KT * BN; i += THREADS) {
        int k = i >> 7, o = i & 127;
        int gi = ((b * 4096) + o0 + o) * KT + k;
        jsm[i] = g_j0[gi];
        g01[i] = make_float2(g_g0[gi], g_g1[gi]);
    }

    // ---- prologue: A for steps 0 (taps 0,1) and 1 (taps 2,3); xs chunk 0 ----
    load_A(sbase + A_OFF, 0, 2, 0, d0, tid);
    load_A(sbase + A_OFF + ASTG, 2, 2, 0, d0, tid);
    load_xs(sbase + XS_OFF, x, b, 0, o0, tid);
    CP_COMMIT();
    CP_WAIT(0);
    __syncthreads();
    build_B(smem, B_OFF, (const float*)(smem + XS_OFF), g01, jsm, 0, 2, tid);
    __syncthreads();

    float acc[2][8][4];
#pragma unroll
    for (int mi = 0; mi < 2; ++mi)
#pragma unroll
        for (int ni = 0; ni < 8; ++ni)
#pragma unroll
            for (int q = 0; q < 4; ++q) acc[mi][ni][q] = 0.f;

    // ---- mainloop: 16 c-chunks x 4 phases (tap pairs 01,23,45, single 6) ----
    for (int cc = 0; cc < 16; ++cc) {
#pragma unroll
        for (int p = 0; p < 4; ++p) {
            const int s = cc * 4 + p;
            // prefetch A for step s+2
            {
                const int p2 = (p + 2) & 3;
                int cc2 = cc + ((p + 2) >> 2);
                if (cc2 >= 16) cc2 = 0;       // tail wrap: harmless, unused
                load_A(sbase + A_OFF + ((s + 2) % 3) * ASTG,
                       2 * p2, (p2 < 3) ? 2 : 1, cc2 * BK, d0, tid);
            }
            // xs for chunk cc+1, issued 3 steps before first use
            if (p == 1 && cc + 1 < 16)
                load_xs(sbase + XS_OFF + ((cc + 1) & 1) * XSTG, x, b,
                        (cc + 1) * BK, o0, tid);
            CP_COMMIT();
            CP_WAIT(2);        // forces group of step s
            __syncthreads();

            // ---- mma for step s ----
            {
                const uint32_t abase = sbase + A_OFF + (s % 3) * ASTG;
                const uint32_t bbase = sbase + B_OFF + (s & 1) * BSTG;
                const int kkmax = (p < 3) ? 4 : 2;
#pragma unroll
                for (int kk = 0; kk < 4; ++kk) {
                    if (kk >= kkmax) break;
                    uint32_t afr[2][4];
#pragma unroll
                    for (int mi = 0; mi < 2; ++mi) {
                        uint32_t addr = abase
                            + (uint32_t)(m_base + mi * 16 + (lane & 15)) * AROW
                            + kk * 32 + (lane & 16);
                        ldsm4(afr[mi][0], afr[mi][1], afr[mi][2], afr[mi][3], addr);
                    }
                    uint32_t bfr[8][2];
#pragma unroll
                    for (int nb = 0; nb < 4; ++nb) {
                        uint32_t addr = bbase
                            + (uint32_t)(n_base + nb * 16 + (lane & 7) + ((lane & 16) >> 1)) * AROW
                            + kk * 32 + ((lane & 8) << 1);
                        ldsm4(bfr[2 * nb][0], bfr[2 * nb][1],
                              bfr[2 * nb + 1][0], bfr[2 * nb + 1][1], addr);
                    }
#pragma unroll
                    for (int ni = 0; ni < 8; ++ni) {
                        mma_f16(acc[0][ni], afr[0], bfr[ni][0], bfr[ni][1]);
                        mma_f16(acc[1][ni], afr[1], bfr[ni][0], bfr[ni][1]);
                    }
                }
            }

            // ---- build B for step s+1 ----
            if (s + 1 < 64) {
                const int pn = (p + 1) & 3;
                const int ccn = cc + ((p + 1) >> 2);
                build_B(smem, B_OFF + ((s + 1) & 1) * BSTG,
                        (const float*)(smem + XS_OFF + (ccn & 1) * XSTG),
                        g01, jsm, 2 * pn, (pn < 3) ? 2 : 1, tid);
            }
            __syncthreads();
        }
    }

    // ---- epilogue: bias add + store ----
    const int qg = lane >> 2, tq = lane & 3;
#pragma unroll
    for (int mi = 0; mi < 2; ++mi) {
        int d = d0 + m_base + mi * 16 + qg;
        float bz0 = bias[d];
        float bz1 = bias[d + 8];
        size_t row0 = ((size_t)b * COUT + d) * OUTL;
        size_t row1 = row0 + (size_t)8 * OUTL;
#pragma unroll
        for (int ni = 0; ni < 8; ++ni) {
            int col = o0 + n_base + ni * 8 + 2 * tq;
            if (col < OUTL) {   // col even, OUTL even => col+1 < OUTL too
                float2 v0 = make_float2(acc[mi][ni][0] + bz0, acc[mi][ni][1] + bz0);
                float2 v1 = make_float2(acc[mi][ni][2] + bz1, acc[mi][ni][3] + bz1);
                *reinterpret_cast<float2*>(out + row0 + col) = v0;
                *reinterpret_cast<float2*>(out + row1 + col) = v1;
            }
        }
    }
}

// ---------------------------------------------------------------------------
extern "C" void kernel_launch(void* const* d_in, const int* in_sizes, int n_in,
                              void* d_out, int out_size) {
    const float* x    = (const float*)d_in[0];
    const float* off  = (const float*)d_in[1];
    const float* w    = (const float*)d_in[2];
    const float* bias = (const float*)d_in[3];
    float* out = (float*)d_out;

    prep_all<<<1344, 256>>>(w, off);

    cudaFuncSetAttribute(deform_mma, cudaFuncAttributeMaxDynamicSharedMemorySize,
                         SMEM_TOTAL);
    dim3 grid(4096 / BN, COUT / BM, BATCH);   // 32 x 2 x 4 = 256 CTAs
    deform_mma<<<grid, THREADS, SMEM_TOTAL>>>(x, bias, out);
}

// round 12
// speedup vs baseline: 1.1756x; 1.0525x over previous
#include <cuda_runtime.h>
#include <cuda_fp16.h>
#include <cstdint>

// ---------------------------------------------------------------------------
// Problem constants
// ---------------------------------------------------------------------------
#define CIN     512
#define COUT    512
#define LIN     4096
#define KT      7
#define OUTL    4090
#define BATCH   4

// Tiling: CTA = 256 (d) x 128 (o). K-step = 64 (32 c x 2 taps), 4 steps per
// c-chunk (last is K=32), 64 steps total. 512 threads, 16 warps (8m x 2n).
#define BM      256
#define BN      128
#define BK      32
#define THREADS 512

// SMEM layout (bytes). Row stride 144B = 9 x 16B -> bank(r) = r mod 8,
// conflict-free ldmatrix. A: 3 stages x 256 x 144. B: 2 stages x 128 x 144.
// xs: 2 stages x 32 rows x 136 floats.
#define AROW    144
#define ASTG    (BM * AROW)        // 36864
#define BSTG    (BN * AROW)        // 18432
#define XROWF   136
#define XROWB   544
#define XSTG    (BK * XROWB)       // 17408

#define A_OFF   0                  // 3 * ASTG = 110592
#define B_OFF   110592             // 2 * BSTG = 36864
#define XS_OFF  147456             // 2 * XSTG = 34816
#define G01_OFF 182272             // 7*128*8 = 7168
#define JSM_OFF 189440             // 7*128*4 = 3584
#define SMEM_TOTAL 193024

// ---------------------------------------------------------------------------
// Scratch (no allocations allowed -> __device__ globals)
// ---------------------------------------------------------------------------
__device__ __half g_wh[(size_t)KT * COUT * CIN];   // [k][d][c] fp16
__device__ float  g_g0[(size_t)BATCH * 4096 * KT];
__device__ float  g_g1[(size_t)BATCH * 4096 * KT];
__device__ int    g_j0[(size_t)BATCH * 4096 * KT];

// ---------------------------------------------------------------------------
// Helpers
// ---------------------------------------------------------------------------
__device__ __forceinline__ uint32_t smem_u32(const void* p) {
    uint32_t a;
    asm("{ .reg .u64 t; cvta.to.shared.u64 t, %1; cvt.u32.u64 %0, t; }" : "=r"(a) : "l"(p));
    return a;
}
__device__ __forceinline__ void cp16(uint32_t dst, const void* src) {
    asm volatile("cp.async.cg.shared.global [%0], [%1], 16;" :: "r"(dst), "l"(src));
}
__device__ __forceinline__ void cp16z(uint32_t dst, const void* src, int nbytes) {
    asm volatile("cp.async.cg.shared.global [%0], [%1], 16, %2;"
                 :: "r"(dst), "l"(src), "r"(nbytes));
}
#define CP_COMMIT() asm volatile("cp.async.commit_group;" ::: "memory")
#define CP_WAIT(N)  asm volatile("cp.async.wait_group %0;" :: "n"(N) : "memory")

__device__ __forceinline__ void ldsm4(uint32_t& r0, uint32_t& r1, uint32_t& r2,
                                      uint32_t& r3, uint32_t addr) {
    asm volatile("ldmatrix.sync.aligned.m8n8.x4.shared.b16 {%0,%1,%2,%3}, [%4];"
                 : "=r"(r0), "=r"(r1), "=r"(r2), "=r"(r3) : "r"(addr));
}
__device__ __forceinline__ void mma_f16(float c[4], const uint32_t a[4],
                                        uint32_t b0, uint32_t b1) {
    asm volatile(
        "mma.sync.aligned.m16n8k16.row.col.f32.f16.f16.f32 "
        "{%0,%1,%2,%3}, {%4,%5,%6,%7}, {%8,%9}, {%0,%1,%2,%3};\n"
        : "+f"(c[0]), "+f"(c[1]), "+f"(c[2]), "+f"(c[3])
        : "r"(a[0]), "r"(a[1]), "r"(a[2]), "r"(a[3]), "r"(b0), "r"(b1));
}

// ---------------------------------------------------------------------------
// Fused prep: blocks [0,896) transpose weights (8 outputs/thread);
// blocks [896,1344) compute gather params.
// ---------------------------------------------------------------------------
__global__ void prep_all(const float* __restrict__ w, const float* __restrict__ off) {
    if (blockIdx.x < 896) {
        int i = blockIdx.x * 256 + threadIdx.x;
        int c0 = (i * 8) & 511;
        int d  = ((i * 8) >> 9) & 511;
        int k  = (i * 8) / (COUT * CIN);
        const float* src = w + ((size_t)d * CIN + c0) * KT + k;
        __half h[8];
#pragma unroll
        for (int q = 0; q < 8; ++q) h[q] = __float2half(src[q * KT]);
        *reinterpret_cast<uint4*>(g_wh + ((size_t)k * COUT + d) * CIN + c0)
            = *reinterpret_cast<const uint4*>(h);
    } else {
        int i = (blockIdx.x - 896) * 256 + threadIdx.x;
        int k = i % KT;
        int o = (i / KT) & 4095;
        int b = i / (KT * 4096);
        float gg0 = 0.f, gg1 = 0.f;
        int j0 = 0;
        if (o < OUTL) {
            float T = (float)(o + k) + off[((size_t)b * OUTL + o) * KT + k];
            T = fmaxf(T, (float)o);
            T = fminf(T, (float)(o + (KT - 1)));
            int U0 = (int)floorf(T);
            if (U0 < 0) U0 = 0;
            if (U0 > LIN - 2) U0 = LIN - 2;
            gg0 = fmaxf(0.f, 1.f - fabsf((float)U0 - T));
            gg1 = fmaxf(0.f, 1.f - fabsf((float)(U0 + 1) - T));
            j0 = U0 - o;
        }
        g_j0[i] = j0;
        g_g0[i] = gg0;
        g_g1[i] = gg1;
    }
}

// ---------------------------------------------------------------------------
// A-tile loader: rows d0..d0+255, K cols = [tap kbase c0..c0+31 | tap kbase+1].
// ---------------------------------------------------------------------------
__device__ __forceinline__ void load_A(uint32_t dbase, int kbase, int kcount,
                                       int c0, int d0, int tid) {
    if (kcount == 2) {
#pragma unroll
        for (int it = 0; it < 4; ++it) {
            int i = tid + it * THREADS;
            int r = i >> 3, ch = i & 7;
            int tap = kbase + (ch >> 2);
            cp16(dbase + r * AROW + ch * 16,
                 g_wh + ((size_t)tap * COUT + d0 + r) * CIN + c0 + (ch & 3) * 8);
        }
    } else {
#pragma unroll
        for (int it = 0; it < 2; ++it) {
            int i = tid + it * THREADS;
            int r = i >> 2, ch = i & 3;
            cp16(dbase + r * AROW + ch * 16,
                 g_wh + ((size_t)kbase * COUT + d0 + r) * CIN + c0 + ch * 8);
        }
    }
}

// ---------------------------------------------------------------------------
// One B-build item (half of a B tile stage). item in {0,1}; item 1 only when
// kcount == 2. Writes B[o][kappa] for cb = item*4 .. item*4+3.
// ---------------------------------------------------------------------------
__device__ __forceinline__ void build_B_item(char* smem, int boff, const float* xsf,
                                             const float2* g01, const int* jsm,
                                             int kbase, int item, int tid) {
    int i = tid + item * THREADS;
    int o = i & 127;
    int cb = i >> 7;
    int tap = kbase + (cb >> 2);
    int base = (cb & 3) * 8 * XROWF + o + jsm[tap * 128 + o];
    float2 g = g01[tap * 128 + o];
    __half2 h[4];
#pragma unroll
    for (int q = 0; q < 4; ++q) {
        float v0 = g.x * xsf[base + (2 * q) * XROWF]
                 + g.y * xsf[base + (2 * q) * XROWF + 1];
        float v1 = g.x * xsf[base + (2 * q + 1) * XROWF]
                 + g.y * xsf[base + (2 * q + 1) * XROWF + 1];
        h[q] = __floats2half2_rn(v0, v1);
    }
    *reinterpret_cast<uint4*>(smem + boff + o * AROW + cb * 16)
        = *reinterpret_cast<uint4*>(h);
}

// ---------------------------------------------------------------------------
// xs loader (cp.async): 32 c-rows x 136-float window at o0.
// ---------------------------------------------------------------------------
__device__ __forceinline__ void load_xs(uint32_t dxb, const float* x, int b,
                                        int c0, int o0, int tid) {
    for (int i = tid; i < 1088; i += THREADS) {
        int r = i / 34, q = i - r * 34;
        int gt0 = o0 + q * 4;
        const float* src = x + ((size_t)(b * CIN + c0 + r)) * LIN + gt0;
        int rem = LIN - gt0;
        int nv = rem >= 4 ? 16 : (rem > 0 ? rem * 4 : 0);
        if (nv == 0) src = x;
        cp16z(dxb + r * XROWB + q * 16, src, nv);
    }
}

// A-fragment loader for one kk phase (both mi tiles).
__device__ __forceinline__ void load_afrag(uint32_t af[2][4], uint32_t abase,
                                           int kk, int m_base, int lane) {
#pragma unroll
    for (int mi = 0; mi < 2; ++mi) {
        uint32_t addr = abase + (uint32_t)(m_base + mi * 16 + (lane & 15)) * AROW
                      + kk * 32 + (lane & 16);
        ldsm4(af[mi][0], af[mi][1], af[mi][2], af[mi][3], addr);
    }
}

// ---------------------------------------------------------------------------
// Main: fp16 mma.sync m16n8k16 fused gather-GEMM, K=64 per step.
// Single barrier per step; build_B interleaved into mma phases; A-fragment
// double buffering across kk.
// ---------------------------------------------------------------------------
__global__ __launch_bounds__(THREADS, 1)
void deform_mma(const float* __restrict__ x, const float* __restrict__ bias,
                float* __restrict__ out) {
    extern __shared__ char smem[];
    const uint32_t sbase = smem_u32(smem);
    float2* g01 = (float2*)(smem + G01_OFF);
    int*    jsm = (int*)(smem + JSM_OFF);

    const int tid  = threadIdx.x;
    const int lane = tid & 31;
    const int wid  = tid >> 5;
    const int o0 = blockIdx.x * BN;
    const int d0 = blockIdx.y * BM;
    const int b  = blockIdx.z;

    const int m_base = (wid & 7) * 32;
    const int n_base = (wid >> 3) * 64;

    // ---- stage gather params ----
    for (int i = tid; i < KT * BN; i += THREADS) {
        int k = i >> 7, o = i & 127;
        int gi = ((b * 4096) + o0 + o) * KT + k;
        jsm[i] = g_j0[gi];
        g01[i] = make_float2(g_g0[gi], g_g1[gi]);
    }

    // ---- prologue: group a = A[0]+xs0; group b = A[1]. Build B[0]. ----
    load_A(sbase + A_OFF, 0, 2, 0, d0, tid);
    load_xs(sbase + XS_OFF, x, b, 0, o0, tid);
    CP_COMMIT();
    load_A(sbase + A_OFF + ASTG, 2, 2, 0, d0, tid);
    CP_COMMIT();
    CP_WAIT(0);
    __syncthreads();
    build_B_item(smem, B_OFF, (const float*)(smem + XS_OFF), g01, jsm, 0, 0, tid);
    build_B_item(smem, B_OFF, (const float*)(smem + XS_OFF), g01, jsm, 0, 1, tid);

    float acc[2][8][4];
#pragma unroll
    for (int mi = 0; mi < 2; ++mi)
#pragma unroll
        for (int ni = 0; ni < 8; ++ni)
#pragma unroll
            for (int q = 0; q < 4; ++q) acc[mi][ni][q] = 0.f;

    // ---- mainloop: 16 c-chunks x 4 phases (tap pairs 01,23,45, single 6) ----
    for (int cc = 0; cc < 16; ++cc) {
#pragma unroll
        for (int p = 0; p < 4; ++p) {
            const int s = cc * 4 + p;
            CP_WAIT(1);        // forces group carrying A[s] (+xs if any)
            __syncthreads();   // visibility + all warps done with step s-1

            // prefetch A for step s+2 (after barrier: old readers are done)
            {
                const int p2 = (p + 2) & 3;
                int cc2 = cc + ((p + 2) >> 2);
                if (cc2 >= 16) cc2 = 0;       // tail wrap: harmless, unused
                load_A(sbase + A_OFF + ((s + 2) % 3) * ASTG,
                       2 * p2, (p2 < 3) ? 2 : 1, cc2 * BK, d0, tid);
            }
            // xs for chunk cc+1 (first consumed by build during step s+2)
            if (p == 1 && cc + 1 < 16)
                load_xs(sbase + XS_OFF + ((cc + 1) & 1) * XSTG, x, b,
                        (cc + 1) * BK, o0, tid);
            CP_COMMIT();

            // ---- compute: mma on (A[s], B[s]); build B[s+1] interleaved ----
            {
                const uint32_t abase = sbase + A_OFF + (s % 3) * ASTG;
                const uint32_t bbase = sbase + B_OFF + (s & 1) * BSTG;
                const int kkmax = (p < 3) ? 4 : 2;

                const int pn = (p + 1) & 3;
                const int ccn = cc + ((p + 1) >> 2);
                const bool do_build = (s + 1 < 64);
                const int nb_kbase = 2 * pn;
                const bool build_item1 = do_build && (pn < 3);
                char* const nb_boff = (char*)0;  // (unused marker)
                (void)nb_boff;
                const int boff_n = B_OFF + ((s + 1) & 1) * BSTG;
                const float* xsf_n = (const float*)(smem + XS_OFF + (ccn & 1) * XSTG);

                uint32_t afr[2][2][4];
                load_afrag(afr[0], abase, 0, m_base, lane);
#pragma unroll
                for (int kk = 0; kk < 4; ++kk) {
                    if (kk >= kkmax) break;
                    const int cur = kk & 1;
                    if (kk + 1 < kkmax)
                        load_afrag(afr[cur ^ 1], abase, kk + 1, m_base, lane);
                    uint32_t bfr[8][2];
#pragma unroll
                    for (int nb = 0; nb < 4; ++nb) {
                        uint32_t addr = bbase
                            + (uint32_t)(n_base + nb * 16 + (lane & 7) + ((lane & 16) >> 1)) * AROW
                            + kk * 32 + ((lane & 8) << 1);
                        ldsm4(bfr[2 * nb][0], bfr[2 * nb][1],
                              bfr[2 * nb + 1][0], bfr[2 * nb + 1][1], addr);
                    }
#pragma unroll
                    for (int ni = 0; ni < 8; ++ni) {
                        mma_f16(acc[0][ni], afr[cur][0], bfr[ni][0], bfr[ni][1]);
                        mma_f16(acc[1][ni], afr[cur][1], bfr[ni][0], bfr[ni][1]);
                    }
                    // interleave B[s+1] build under the mma stream
                    if (kk == 0 && do_build)
                        build_B_item(smem, boff_n, xsf_n, g01, jsm, nb_kbase, 0, tid);
                    if (kk == 1 && build_item1)
                        build_B_item(smem, boff_n, xsf_n, g01, jsm, nb_kbase, 1, tid);
                }
            }
        }
    }

    // ---- epilogue: bias add + store ----
    const int qg = lane >> 2, tq = lane & 3;
#pragma unroll
    for (int mi = 0; mi < 2; ++mi) {
        int d = d0 + m_base + mi * 16 + qg;
        float bz0 = bias[d];
        float bz1 = bias[d + 8];
        size_t row0 = ((size_t)b * COUT + d) * OUTL;
        size_t row1 = row0 + (size_t)8 * OUTL;
#pragma unroll
        for (int ni = 0; ni < 8; ++ni) {
            int col = o0 + n_base + ni * 8 + 2 * tq;
            if (col < OUTL) {   // col even, OUTL even => col+1 < OUTL too
                float2 v0 = make_float2(acc[mi][ni][0] + bz0, acc[mi][ni][1] + bz0);
                float2 v1 = make_float2(acc[mi][ni][2] + bz1, acc[mi][ni][3] + bz1);
                *reinterpret_cast<float2*>(out + row0 + col) = v0;
                *reinterpret_cast<float2*>(out + row1 + col) = v1;
            }
        }
    }
}

// ---------------------------------------------------------------------------
extern "C" void kernel_launch(void* const* d_in, const int* in_sizes, int n_in,
                              void* d_out, int out_size) {
    const float* x    = (const float*)d_in[0];
    const float* off  = (const float*)d_in[1];
    const float* w    = (const float*)d_in[2];
    const float* bias = (const float*)d_in[3];
    float* out = (float*)d_out;

    prep_all<<<1344, 256>>>(w, off);

    cudaFuncSetAttribute(deform_mma, cudaFuncAttributeMaxDynamicSharedMemorySize,
                         SMEM_TOTAL);
    dim3 grid(4096 / BN, COUT / BM, BATCH);   // 32 x 2 x 4 = 256 CTAs
    deform_mma<<<grid, THREADS, SMEM_TOTAL>>>(x, bias, out);
}

// round 13
// speedup vs baseline: 1.1879x; 1.0105x over previous
#include <cuda_runtime.h>
#include <cuda_fp16.h>
#include <cstdint>

// ---------------------------------------------------------------------------
// Problem constants
// ---------------------------------------------------------------------------
#define CIN     512
#define COUT    512
#define LIN     4096
#define KT      7
#define OUTL    4090
#define BATCH   4

// Tiling: CTA = 256 (d) x 128 (o). K-step = 64 (32 c x 2 taps), 64 steps.
// 256 threads, 8 warps (4m x 2n), warp tile 64 x 64.
#define BM      256
#define BN      128
#define BK      32
#define THREADS 256

// SMEM layout (bytes). Row stride 144B = 9 x 16B -> bank(r) = r mod 8,
// conflict-free ldmatrix. A: 3 stages x 256 x 144. B: 2 stages x 128 x 144.
// xs: fp16, 2 stages x 32 rows x 144 halves (288B rows).
#define AROW    144
#define ASTG    (BM * AROW)        // 36864
#define BSTG    (BN * AROW)        // 18432
#define XROWH   144                // halves per xs row (288B stride; 136 used)
#define XROWB   288
#define XSTG    (BK * XROWB)       // 9216

#define A_OFF   0                  // 3 * ASTG = 110592
#define B_OFF   110592             // 2 * BSTG = 36864
#define XS_OFF  147456             // 2 * XSTG = 18432
#define G01_OFF 165888             // 7*128*8 = 7168
#define JSM_OFF 173056             // 7*128*4 = 3584
#define SMEM_TOTAL 176640

// ---------------------------------------------------------------------------
// Scratch (no allocations allowed -> __device__ globals)
// ---------------------------------------------------------------------------
__device__ __half g_wh[(size_t)KT * COUT * CIN];      // [k][d][c] fp16
__device__ __half g_xh[(size_t)BATCH * CIN * LIN];    // fp16 copy of x
__device__ float  g_g0[(size_t)BATCH * 4096 * KT];
__device__ float  g_g1[(size_t)BATCH * 4096 * KT];
__device__ int    g_j0[(size_t)BATCH * 4096 * KT];

// ---------------------------------------------------------------------------
// Helpers
// ---------------------------------------------------------------------------
__device__ __forceinline__ uint32_t smem_u32(const void* p) {
    uint32_t a;
    asm("{ .reg .u64 t; cvta.to.shared.u64 t, %1; cvt.u32.u64 %0, t; }" : "=r"(a) : "l"(p));
    return a;
}
__device__ __forceinline__ void cp16(uint32_t dst, const void* src) {
    asm volatile("cp.async.cg.shared.global [%0], [%1], 16;" :: "r"(dst), "l"(src));
}
__device__ __forceinline__ void cp16z(uint32_t dst, const void* src, int nbytes) {
    asm volatile("cp.async.cg.shared.global [%0], [%1], 16, %2;"
                 :: "r"(dst), "l"(src), "r"(nbytes));
}
#define CP_COMMIT() asm volatile("cp.async.commit_group;" ::: "memory")
#define CP_WAIT(N)  asm volatile("cp.async.wait_group %0;" :: "n"(N) : "memory")

__device__ __forceinline__ void ldsm4(uint32_t& r0, uint32_t& r1, uint32_t& r2,
                                      uint32_t& r3, uint32_t addr) {
    asm volatile("ldmatrix.sync.aligned.m8n8.x4.shared.b16 {%0,%1,%2,%3}, [%4];"
                 : "=r"(r0), "=r"(r1), "=r"(r2), "=r"(r3) : "r"(addr));
}
__device__ __forceinline__ void mma_f16(float c[4], const uint32_t a[4],
                                        uint32_t b0, uint32_t b1) {
    asm volatile(
        "mma.sync.aligned.m16n8k16.row.col.f32.f16.f16.f32 "
        "{%0,%1,%2,%3}, {%4,%5,%6,%7}, {%8,%9}, {%0,%1,%2,%3};\n"
        : "+f"(c[0]), "+f"(c[1]), "+f"(c[2]), "+f"(c[3])
        : "r"(a[0]), "r"(a[1]), "r"(a[2]), "r"(a[3]), "r"(b0), "r"(b1));
}

// ---------------------------------------------------------------------------
// Fused prep:
//   blocks [0,896)     : weight transpose w[d][c][k] -> g_wh[k][d][c]
//   blocks [896,1344)  : gather params
//   blocks [1344,5440) : x fp32 -> fp16 convert (8 elts/thread)
// ---------------------------------------------------------------------------
__global__ void prep_all(const float* __restrict__ w, const float* __restrict__ off,
                         const float* __restrict__ x) {
    if (blockIdx.x < 896) {
        int i = blockIdx.x * 256 + threadIdx.x;
        int c0 = (i * 8) & 511;
        int d  = ((i * 8) >> 9) & 511;
        int k  = (i * 8) / (COUT * CIN);
        const float* src = w + ((size_t)d * CIN + c0) * KT + k;
        __half h[8];
#pragma unroll
        for (int q = 0; q < 8; ++q) h[q] = __float2half(src[q * KT]);
        *reinterpret_cast<uint4*>(g_wh + ((size_t)k * COUT + d) * CIN + c0)
            = *reinterpret_cast<const uint4*>(h);
    } else if (blockIdx.x < 1344) {
        int i = (blockIdx.x - 896) * 256 + threadIdx.x;
        int k = i % KT;
        int o = (i / KT) & 4095;
        int b = i / (KT * 4096);
        float gg0 = 0.f, gg1 = 0.f;
        int j0 = 0;
        if (o < OUTL) {
            float T = (float)(o + k) + off[((size_t)b * OUTL + o) * KT + k];
            T = fmaxf(T, (float)o);
            T = fminf(T, (float)(o + (KT - 1)));
            int U0 = (int)floorf(T);
            if (U0 < 0) U0 = 0;
            if (U0 > LIN - 2) U0 = LIN - 2;
            gg0 = fmaxf(0.f, 1.f - fabsf((float)U0 - T));
            gg1 = fmaxf(0.f, 1.f - fabsf((float)(U0 + 1) - T));
            j0 = U0 - o;
        }
        g_j0[i] = j0;
        g_g0[i] = gg0;
        g_g1[i] = gg1;
    } else {
        size_t i = ((size_t)(blockIdx.x - 1344) * 256 + threadIdx.x) * 8;
        float4 v0 = *reinterpret_cast<const float4*>(x + i);
        float4 v1 = *reinterpret_cast<const float4*>(x + i + 4);
        __half h[8];
        h[0] = __float2half(v0.x); h[1] = __float2half(v0.y);
        h[2] = __float2half(v0.z); h[3] = __float2half(v0.w);
        h[4] = __float2half(v1.x); h[5] = __float2half(v1.y);
        h[6] = __float2half(v1.z); h[7] = __float2half(v1.w);
        *reinterpret_cast<uint4*>(g_xh + i) = *reinterpret_cast<const uint4*>(h);
    }
}

// ---------------------------------------------------------------------------
// A-tile loader: rows d0..d0+255, K cols = [tap kbase c0..c0+31 | tap kbase+1].
// ---------------------------------------------------------------------------
__device__ __forceinline__ void load_A(uint32_t dbase, int kbase, int kcount,
                                       int c0, int d0, int tid) {
    if (kcount == 2) {
#pragma unroll
        for (int it = 0; it < 8; ++it) {
            int i = tid + it * THREADS;
            int r = i >> 3, ch = i & 7;
            int tap = kbase + (ch >> 2);
            cp16(dbase + r * AROW + ch * 16,
                 g_wh + ((size_t)tap * COUT + d0 + r) * CIN + c0 + (ch & 3) * 8);
        }
    } else {
#pragma unroll
        for (int it = 0; it < 4; ++it) {
            int i = tid + it * THREADS;
            int r = i >> 2, ch = i & 3;
            cp16(dbase + r * AROW + ch * 16,
                 g_wh + ((size_t)kbase * COUT + d0 + r) * CIN + c0 + ch * 8);
        }
    }
}

// ---------------------------------------------------------------------------
// One B-build item: item in {0..3}; covers cb = 2*item + (tid>>7) (two cb
// groups of 8 kappa halves each). xs is fp16.
// ---------------------------------------------------------------------------
__device__ __forceinline__ void build_B_item(char* smem, int boff, const __half* xsf,
                                             const float2* g01, const int* jsm,
                                             int kbase, int item, int tid) {
    int i = tid + item * THREADS;
    int o = i & 127;
    int cb = i >> 7;                 // 0..7 across items
    int tap = kbase + (cb >> 2);
    int base = (cb & 3) * 8 * XROWH + o + jsm[tap * 128 + o];
    float2 g = g01[tap * 128 + o];
    __half2 h[4];
#pragma unroll
    for (int q = 0; q < 4; ++q) {
        float v0 = g.x * __half2float(xsf[base + (2 * q) * XROWH])
                 + g.y * __half2float(xsf[base + (2 * q) * XROWH + 1]);
        float v1 = g.x * __half2float(xsf[base + (2 * q + 1) * XROWH])
                 + g.y * __half2float(xsf[base + (2 * q + 1) * XROWH + 1]);
        h[q] = __floats2half2_rn(v0, v1);
    }
    *reinterpret_cast<uint4*>(smem + boff + o * AROW + cb * 16)
        = *reinterpret_cast<uint4*>(h);
}

// ---------------------------------------------------------------------------
// xs loader (cp.async, fp16 source): 32 c-rows x 136-half window at o0.
// ---------------------------------------------------------------------------
__device__ __forceinline__ void load_xs(uint32_t dxb, int b, int c0, int o0,
                                        int tid) {
    for (int i = tid; i < 544; i += THREADS) {
        int r = i / 17, q = i - r * 17;
        int gt0 = o0 + q * 8;
        const __half* src = g_xh + ((size_t)(b * CIN + c0 + r)) * LIN + gt0;
        int rem = LIN - gt0;
        int nv = rem >= 8 ? 16 : (rem > 0 ? rem * 2 : 0);
        if (nv == 0) src = g_xh;
        cp16z(dxb + r * XROWB + q * 16, src, nv);
    }
}

// ---------------------------------------------------------------------------
// Main: fp16 mma.sync m16n8k16 fused gather-GEMM. Warp tile 64x64 (4m x 2n),
// K=64 per step, single barrier per step, builds interleaved per kk phase.
// ---------------------------------------------------------------------------
__global__ __launch_bounds__(THREADS, 1)
void deform_mma(const float* __restrict__ bias, float* __restrict__ out) {
    extern __shared__ char smem[];
    const uint32_t sbase = smem_u32(smem);
    float2* g01 = (float2*)(smem + G01_OFF);
    int*    jsm = (int*)(smem + JSM_OFF);

    const int tid  = threadIdx.x;
    const int lane = tid & 31;
    const int wid  = tid >> 5;
    const int o0 = blockIdx.x * BN;
    const int d0 = blockIdx.y * BM;
    const int b  = blockIdx.z;

    const int m_base = (wid & 3) * 64;
    const int n_base = (wid >> 2) * 64;

    // ---- stage gather params ----
    for (int i = tid; i < KT * BN; i += THREADS) {
        int k = i >> 7, o = i & 127;
        int gi = ((b * 4096) + o0 + o) * KT + k;
        jsm[i] = g_j0[gi];
        g01[i] = make_float2(g_g0[gi], g_g1[gi]);
    }

    // ---- prologue: group a = A[0]+xs0; group b = A[1]. Build B[0]. ----
    load_A(sbase + A_OFF, 0, 2, 0, d0, tid);
    load_xs(sbase + XS_OFF, b, 0, 0 + o0 * 0 + o0, tid);
    CP_COMMIT();
    load_A(sbase + A_OFF + ASTG, 2, 2, 0, d0, tid);
    CP_COMMIT();
    CP_WAIT(0);
    __syncthreads();
#pragma unroll
    for (int it = 0; it < 4; ++it)
        build_B_item(smem, B_OFF, (const __half*)(smem + XS_OFF), g01, jsm, 0, it, tid);

    float acc[4][8][4];
#pragma unroll
    for (int mi = 0; mi < 4; ++mi)
#pragma unroll
        for (int ni = 0; ni < 8; ++ni)
#pragma unroll
            for (int q = 0; q < 4; ++q) acc[mi][ni][q] = 0.f;

    // ---- mainloop: 16 c-chunks x 4 phases (tap pairs 01,23,45, single 6) ----
    for (int cc = 0; cc < 16; ++cc) {
#pragma unroll
        for (int p = 0; p < 4; ++p) {
            const int s = cc * 4 + p;
            CP_WAIT(1);        // forces group carrying A[s] (+xs if any)
            __syncthreads();   // visibility + all warps done with step s-1

            // prefetch A for step s+2
            {
                const int p2 = (p + 2) & 3;
                int cc2 = cc + ((p + 2) >> 2);
                if (cc2 >= 16) cc2 = 0;       // tail wrap: harmless, unused
                load_A(sbase + A_OFF + ((s + 2) % 3) * ASTG,
                       2 * p2, (p2 < 3) ? 2 : 1, cc2 * BK, d0, tid);
            }
            // xs for chunk cc+1 (first consumed by build during step cc*4+3)
            if (p == 1 && cc + 1 < 16)
                load_xs(sbase + XS_OFF + ((cc + 1) & 1) * XSTG, b,
                        (cc + 1) * BK, o0, tid);
            CP_COMMIT();

            // ---- compute: mma on (A[s], B[s]); build B[s+1] interleaved ----
            {
                const uint32_t abase = sbase + A_OFF + (s % 3) * ASTG;
                const uint32_t bbase = sbase + B_OFF + (s & 1) * BSTG;
                const int kkmax = (p < 3) ? 4 : 2;

                const int pn = (p + 1) & 3;
                const int ccn = cc + ((p + 1) >> 2);
                const bool do_build = (s + 1 < 64);
                const int nb_kbase = 2 * pn;
                const int nitems = (pn < 3) ? 4 : 2;
                const int boff_n = B_OFF + ((s + 1) & 1) * BSTG;
                const __half* xsf_n = (const __half*)(smem + XS_OFF + (ccn & 1) * XSTG);

#pragma unroll
                for (int kk = 0; kk < 4; ++kk) {
                    if (kk >= kkmax) break;
                    uint32_t afr[4][4];
#pragma unroll
                    for (int mi = 0; mi < 4; ++mi) {
                        uint32_t addr = abase
                            + (uint32_t)(m_base + mi * 16 + (lane & 15)) * AROW
                            + kk * 32 + (lane & 16);
                        ldsm4(afr[mi][0], afr[mi][1], afr[mi][2], afr[mi][3], addr);
                    }
                    uint32_t bfr[8][2];
#pragma unroll
                    for (int nb = 0; nb < 4; ++nb) {
                        uint32_t addr = bbase
                            + (uint32_t)(n_base + nb * 16 + (lane & 7) + ((lane & 16) >> 1)) * AROW
                            + kk * 32 + ((lane & 8) << 1);
                        ldsm4(bfr[2 * nb][0], bfr[2 * nb][1],
                              bfr[2 * nb + 1][0], bfr[2 * nb + 1][1], addr);
                    }
#pragma unroll
                    for (int ni = 0; ni < 8; ++ni) {
#pragma unroll
                        for (int mi = 0; mi < 4; ++mi)
                            mma_f16(acc[mi][ni], afr[mi], bfr[ni][0], bfr[ni][1]);
                    }
                    // interleave B[s+1] build items under the mma stream
                    if (do_build) {
                        if (kkmax == 4) {
                            if (kk < nitems)
                                build_B_item(smem, boff_n, xsf_n, g01, jsm,
                                             nb_kbase, kk, tid);
                        } else {  // kkmax == 2 -> pn == 0 -> nitems == 4
                            build_B_item(smem, boff_n, xsf_n, g01, jsm,
                                         nb_kbase, 2 * kk, tid);
                            build_B_item(smem, boff_n, xsf_n, g01, jsm,
                                         nb_kbase, 2 * kk + 1, tid);
                        }
                    }
                }
            }
        }
    }

    // ---- epilogue: bias add + store ----
    const int qg = lane >> 2, tq = lane & 3;
#pragma unroll
    for (int mi = 0; mi < 4; ++mi) {
        int d = d0 + m_base + mi * 16 + qg;
        float bz0 = bias[d];
        float bz1 = bias[d + 8];
        size_t row0 = ((size_t)b * COUT + d) * OUTL;
        size_t row1 = row0 + (size_t)8 * OUTL;
#pragma unroll
        for (int ni = 0; ni < 8; ++ni) {
            int col = o0 + n_base + ni * 8 + 2 * tq;
            if (col < OUTL) {   // col even, OUTL even => col+1 < OUTL too
                float2 v0 = make_float2(acc[mi][ni][0] + bz0, acc[mi][ni][1] + bz0);
                float2 v1 = make_float2(acc[mi][ni][2] + bz1, acc[mi][ni][3] + bz1);
                *reinterpret_cast<float2*>(out + row0 + col) = v0;
                *reinterpret_cast<float2*>(out + row1 + col) = v1;
            }
        }
    }
}

// ---------------------------------------------------------------------------
extern "C" void kernel_launch(void* const* d_in, const int* in_sizes, int n_in,
                              void* d_out, int out_size) {
    const float* x    = (const float*)d_in[0];
    const float* off  = (const float*)d_in[1];
    const float* w    = (const float*)d_in[2];
    const float* bias = (const float*)d_in[3];
    float* out = (float*)d_out;

    prep_all<<<5440, 256>>>(w, off, x);

    cudaFuncSetAttribute(deform_mma, cudaFuncAttributeMaxDynamicSharedMemorySize,
                         SMEM_TOTAL);
    dim3 grid(4096 / BN, COUT / BM, BATCH);   // 32 x 2 x 4 = 256 CTAs
    deform_mma<<<grid, THREADS, SMEM_TOTAL>>>(bias, out);
}